// round 9
// baseline (speedup 1.0000x reference)
#include <cuda_runtime.h>
#include <cstdint>

// Problem constants
#define DIMM   1024
#define BATCH  4
#define SEQ    2048
#define NHEAD  16
#define HDIM   64
#define MTOK   (BATCH*SEQ)        // 8192
#define NQKV   (3*DIMM)           // 3072
#define PLANE  (BATCH*NHEAD*SEQ*HDIM)  // 8388608 floats per Q/K/V plane

// Q pre-scale: 1/sqrt(64) * log2(e)  (softmax done in exp2 domain)
#define QSCALE 0.18033688011112042f

// Scratch (device globals: allocation-free per harness rules)
__device__ float g_QKV[3ULL * PLANE];            // [3][B][H][S][hd] (tf32-rounded)
__device__ float g_O[(size_t)MTOK * DIMM];       // [B,S,D] attention out (tf32-rounded)
__device__ float g_x [(size_t)MTOK * DIMM];      // tf32-rounded x
__device__ float g_Wq[(size_t)DIMM * NQKV];      // tf32-rounded W_qkv
__device__ float g_Wp[(size_t)DIMM * DIMM];      // tf32-rounded W_proj

// ---------------------------------------------------------------------------
// helpers
// ---------------------------------------------------------------------------
__device__ __forceinline__ float tfr(float x) {   // round-to-nearest tf32, as float
    unsigned u;
    asm("cvt.rna.tf32.f32 %0, %1;" : "=r"(u) : "f"(x));
    return __uint_as_float(u);
}

// mma.m16n8k8 tf32: operands already tf32-rounded -> HW truncation is lossless.
__device__ __forceinline__ void mma_tf32(float* c, const unsigned* a, unsigned b0, unsigned b1) {
    asm volatile(
        "mma.sync.aligned.m16n8k8.row.col.f32.tf32.tf32.f32 "
        "{%0,%1,%2,%3}, {%4,%5,%6,%7}, {%8,%9}, {%0,%1,%2,%3};"
        : "+f"(c[0]), "+f"(c[1]), "+f"(c[2]), "+f"(c[3])
        : "r"(a[0]), "r"(a[1]), "r"(a[2]), "r"(a[3]), "r"(b0), "r"(b1));
}

__device__ __forceinline__ void cp16(void* smem, const void* gmem) {
    unsigned sa = (unsigned)__cvta_generic_to_shared(smem);
    asm volatile("cp.async.cg.shared.global [%0], [%1], 16;" :: "r"(sa), "l"(gmem));
}
#define CP_COMMIT()     asm volatile("cp.async.commit_group;")
#define CP_WAIT(n)      asm volatile("cp.async.wait_group %0;" :: "n"(n))

// ---------------------------------------------------------------------------
// Pre-pass: tf32-round inputs into device-global copies. WHICH: 0=x 1=Wq 2=Wp
// ---------------------------------------------------------------------------
template<int WHICH>
__global__ void round_prepass(const float* __restrict__ src, int n4)
{
    float* dst = (WHICH == 0) ? g_x : (WHICH == 1) ? g_Wq : g_Wp;
    int i = blockIdx.x * blockDim.x + threadIdx.x;
    if (i < n4) {
        float4 v = ((const float4*)src)[i];
        v.x = tfr(v.x); v.y = tfr(v.y); v.z = tfr(v.z); v.w = tfr(v.w);
        ((float4*)dst)[i] = v;
    }
}

// ---------------------------------------------------------------------------
// Tensor-core GEMM, cp.async 3-stage ring, ONE barrier per k-tile.
// C[128x128] = A @ W (+bias). BK=32, 256 threads, 8 warps 2(m) x 4(n).
// Ordering proof: loads for tile i+2 are issued AFTER compute(i); every warp
// issuing them has passed sync(i), which all warps reach only after finishing
// compute(i-1) — the last consumer of that buffer. Visibility: WAIT + sync
// precede compute.
// ---------------------------------------------------------------------------
#define AS_STR 36     // frag addr mod32 = 4g+t  (conflict-free)
#define BS_STR 136    // frag addr mod32 = 8t+g  (conflict-free)
#define AS_WORDS (128*AS_STR)   // 4608
#define BS_WORDS (32*BS_STR)    // 4352
#define GSTAGE_WORDS (AS_WORDS + BS_WORDS)

extern __shared__ unsigned dyn_smem[];

template<bool QKV>
__global__ __launch_bounds__(256, 2) void gemm_mma_kernel(
    const float* __restrict__ bias, float* __restrict__ out)
{
    constexpr int NC = QKV ? NQKV : DIMM;
    const float* __restrict__ A = QKV ? (const float*)g_x : (const float*)g_O;
    const float* __restrict__ W = QKV ? (const float*)g_Wq : (const float*)g_Wp;

    const int tid  = threadIdx.x;
    const int lane = tid & 31;
    const int warp = tid >> 5;
    const int g  = lane >> 2;
    const int t4 = lane & 3;
    const int m0 = (warp & 1) * 64;
    const int n0 = (warp >> 1) * 32;
    const int rowbase = blockIdx.y * 128;
    const int colbase = blockIdx.x * 128;

    auto load_tile = [&](int buf, int k0) {
        unsigned* As = dyn_smem + buf * GSTAGE_WORDS;
        unsigned* Bs = As + AS_WORDS;
#pragma unroll
        for (int it = 0; it < 4; it++) {
            int flat = tid + it * 256;
            int r  = flat >> 3;
            int c4 = (flat & 7) * 4;
            cp16(&As[r * AS_STR + c4], &A[(size_t)(rowbase + r) * DIMM + k0 + c4]);
        }
#pragma unroll
        for (int it = 0; it < 4; it++) {
            int flat = tid + it * 256;
            int r  = flat >> 5;
            int c4 = (flat & 31) * 4;
            cp16(&Bs[r * BS_STR + c4], &W[(size_t)(k0 + r) * NC + colbase + c4]);
        }
    };

    float acc[4][4][4];
#pragma unroll
    for (int mi = 0; mi < 4; mi++)
#pragma unroll
        for (int ni = 0; ni < 4; ni++)
#pragma unroll
            for (int r = 0; r < 4; r++) acc[mi][ni][r] = 0.f;

    load_tile(0, 0);  CP_COMMIT();
    load_tile(1, 32); CP_COMMIT();

    constexpr int NT = DIMM / 32;   // 32 k-tiles
#pragma unroll 1
    for (int i = 0; i < NT; i++) {
        if (i + 1 < NT) { CP_WAIT(1); } else { CP_WAIT(0); }
        __syncthreads();             // ONE barrier per iteration

        const unsigned* As = dyn_smem + (i % 3) * GSTAGE_WORDS;
        const unsigned* Bs = As + AS_WORDS;
#pragma unroll
        for (int ks = 0; ks < 4; ks++) {
            const int kk = ks * 8;
            unsigned af[4][4];
#pragma unroll
            for (int mi = 0; mi < 4; mi++) {
                int row = m0 + mi * 16 + g;
                af[mi][0] = As[(row    ) * AS_STR + kk + t4];
                af[mi][1] = As[(row + 8) * AS_STR + kk + t4];
                af[mi][2] = As[(row    ) * AS_STR + kk + t4 + 4];
                af[mi][3] = As[(row + 8) * AS_STR + kk + t4 + 4];
            }
            unsigned bf[4][2];
#pragma unroll
            for (int ni = 0; ni < 4; ni++) {
                int col = n0 + ni * 8 + g;
                bf[ni][0] = Bs[(kk + t4    ) * BS_STR + col];
                bf[ni][1] = Bs[(kk + t4 + 4) * BS_STR + col];
            }
#pragma unroll
            for (int mi = 0; mi < 4; mi++)
#pragma unroll
                for (int ni = 0; ni < 4; ni++)
                    mma_tf32(acc[mi][ni], af[mi], bf[ni][0], bf[ni][1]);
        }

        if (i + 2 < NT) {            // safe: after compute, past sync(i)
            load_tile((i + 2) % 3, (i + 2) * 32);
            CP_COMMIT();
        }
    }

    // Epilogue
#pragma unroll
    for (int mi = 0; mi < 4; mi++) {
#pragma unroll
        for (int half = 0; half < 2; half++) {
            int m = rowbase + m0 + mi * 16 + g + half * 8;
#pragma unroll
            for (int ni = 0; ni < 4; ni++) {
                int c  = colbase + n0 + ni * 8 + 2 * t4;
                float v0 = acc[mi][ni][half * 2 + 0] + bias[c];
                float v1 = acc[mi][ni][half * 2 + 1] + bias[c + 1];
                if (QKV) {
                    int which = c >> 10;
                    int d     = c & 1023;
                    int h     = d >> 6;
                    int dd    = d & 63;
                    float sc  = (which == 0) ? QSCALE : 1.0f;
                    int b_ = m >> 11;
                    int s  = m & 2047;
                    size_t dst = (size_t)which * PLANE +
                                 (((size_t)(b_ * NHEAD + h) * SEQ + s) * HDIM) + dd;
                    *(float2*)&g_QKV[dst] = make_float2(tfr(v0 * sc), tfr(v1 * sc));
                } else {
                    *(float2*)&out[(size_t)m * DIMM + c] = make_float2(v0, v1);
                }
            }
        }
    }
}

// ---------------------------------------------------------------------------
// Flash attention. 2-stage cp.async KV ring (2 CTAs/SM for overlap), raw-bit
// tf32 (operands pre-rounded), exp2 softmax. P passes from S-MMA C-fragments
// to O-MMA A-fragments via intra-quad shuffles — no SMEM round trip.
// ---------------------------------------------------------------------------
#define KS_STR 68     // K frag addr mod32 = 4g+t (conflict-free)
#define VS_STR 72     // V frag addr mod32 = 8t+g (conflict-free)
#define QS_STR 68
#define KS_WORDS (64*KS_STR)    // 4352
#define VS_WORDS (64*VS_STR)    // 4608
#define FSTAGE_WORDS (KS_WORDS + VS_WORDS)

__global__ __launch_bounds__(256, 2) void flash_mma_kernel()
{
    unsigned* KVB = dyn_smem;                               // [2][FSTAGE_WORDS]
    float*    Qs  = (float*)(dyn_smem + 2 * FSTAGE_WORDS);  // [128][QS_STR]

    const int bh  = blockIdx.x;
    const int qb  = blockIdx.y;
    const int tid = threadIdx.x;
    const int lane = tid & 31;
    const int warp = tid >> 5;
    const int g  = lane >> 2;
    const int t4 = lane & 3;
    const int w16 = warp * 16;

    const float* Qg = g_QKV + ((size_t)bh * SEQ + qb * 128) * HDIM;
    const float* Kg = g_QKV + (size_t)PLANE     + (size_t)bh * SEQ * HDIM;
    const float* Vg = g_QKV + (size_t)2 * PLANE + (size_t)bh * SEQ * HDIM;

    auto load_kv = [&](int buf, int kt) {
        unsigned* Ks = KVB + buf * FSTAGE_WORDS;
        unsigned* Vs = Ks + KS_WORDS;
#pragma unroll
        for (int it = 0; it < 4; it++) {
            int flat = tid + it * 256;
            int r  = flat >> 4;
            int c4 = (flat & 15) * 4;
            size_t gsrc = ((size_t)kt * 64 + r) * HDIM + c4;
            cp16(&Ks[r * KS_STR + c4], &Kg[gsrc]);
            cp16(&Vs[r * VS_STR + c4], &Vg[gsrc]);
        }
    };

    load_kv(0, 0);
    CP_COMMIT();

    // Stage Q (128x64; pre-rounded + pre-scaled in GEMM1)
#pragma unroll
    for (int it = 0; it < 8; it++) {
        int flat = tid + it * 256;
        int r  = flat >> 4;
        int c4 = (flat & 15) * 4;
        *(float4*)&Qs[r * QS_STR + c4] = *(const float4*)&Qg[(size_t)r * HDIM + c4];
    }
    __syncthreads();

    unsigned aq[8][4];
#pragma unroll
    for (int ks = 0; ks < 8; ks++) {
        int kk = ks * 8;
        aq[ks][0] = __float_as_uint(Qs[(w16 + g    ) * QS_STR + kk + t4]);
        aq[ks][1] = __float_as_uint(Qs[(w16 + g + 8) * QS_STR + kk + t4]);
        aq[ks][2] = __float_as_uint(Qs[(w16 + g    ) * QS_STR + kk + t4 + 4]);
        aq[ks][3] = __float_as_uint(Qs[(w16 + g + 8) * QS_STR + kk + t4 + 4]);
    }

    float m_[2] = {-1e30f, -1e30f};
    float l_[2] = {0.f, 0.f};
    float o[8][4];
#pragma unroll
    for (int ni = 0; ni < 8; ni++)
#pragma unroll
        for (int r = 0; r < 4; r++) o[ni][r] = 0.f;

    constexpr int NT = SEQ / 64;   // 32 KV tiles
#pragma unroll 1
    for (int kt = 0; kt < NT; kt++) {
        if (kt + 1 < NT) {
            load_kv((kt + 1) & 1, kt + 1);
            CP_COMMIT();
            CP_WAIT(1);
        } else {
            CP_WAIT(0);
        }
        __syncthreads();

        const unsigned* Ks = KVB + (kt & 1) * FSTAGE_WORDS;
        const unsigned* Vs = Ks + KS_WORDS;

        // S = Q @ K^T (log2-domain scores; Q pre-scaled)
        float s[8][4];
#pragma unroll
        for (int ni = 0; ni < 8; ni++)
#pragma unroll
            for (int r = 0; r < 4; r++) s[ni][r] = 0.f;

#pragma unroll
        for (int ni = 0; ni < 8; ni++) {
            const unsigned* kb = &Ks[(size_t)(ni * 8 + g) * KS_STR];
#pragma unroll
            for (int ks = 0; ks < 8; ks++) {
                mma_tf32(s[ni], aq[ks], kb[ks * 8 + t4], kb[ks * 8 + t4 + 4]);
            }
        }

        // Online softmax (exp2 domain), rows g and g+8, reduce over 4 t-lanes
        float mx0 = -1e30f, mx1 = -1e30f;
#pragma unroll
        for (int ni = 0; ni < 8; ni++) {
            mx0 = fmaxf(mx0, fmaxf(s[ni][0], s[ni][1]));
            mx1 = fmaxf(mx1, fmaxf(s[ni][2], s[ni][3]));
        }
        mx0 = fmaxf(mx0, __shfl_xor_sync(0xffffffffu, mx0, 1));
        mx0 = fmaxf(mx0, __shfl_xor_sync(0xffffffffu, mx0, 2));
        mx1 = fmaxf(mx1, __shfl_xor_sync(0xffffffffu, mx1, 1));
        mx1 = fmaxf(mx1, __shfl_xor_sync(0xffffffffu, mx1, 2));

        float mn0 = fmaxf(m_[0], mx0);
        float mn1 = fmaxf(m_[1], mx1);
        float corr0 = exp2f(m_[0] - mn0);
        float corr1 = exp2f(m_[1] - mn1);
        m_[0] = mn0; m_[1] = mn1;

        // P rounded to tf32; denominator summed from the SAME rounded values.
        float lp0 = 0.f, lp1 = 0.f;
#pragma unroll
        for (int ni = 0; ni < 8; ni++) {
            s[ni][0] = tfr(exp2f(s[ni][0] - mn0));
            s[ni][1] = tfr(exp2f(s[ni][1] - mn0));
            s[ni][2] = tfr(exp2f(s[ni][2] - mn1));
            s[ni][3] = tfr(exp2f(s[ni][3] - mn1));
            lp0 += s[ni][0] + s[ni][1];
            lp1 += s[ni][2] + s[ni][3];
            o[ni][0] *= corr0; o[ni][1] *= corr0;
            o[ni][2] *= corr1; o[ni][3] *= corr1;
        }
        lp0 += __shfl_xor_sync(0xffffffffu, lp0, 1);
        lp0 += __shfl_xor_sync(0xffffffffu, lp0, 2);
        lp1 += __shfl_xor_sync(0xffffffffu, lp1, 1);
        lp1 += __shfl_xor_sync(0xffffffffu, lp1, 2);
        l_[0] = l_[0] * corr0 + lp0;
        l_[1] = l_[1] * corr1 + lp1;

        // O += P @ V. C-frag -> A-frag via intra-quad shuffles:
        // A elem (row g, col 8ks+c) lives in lane (lane&~3)+(c>>1),
        // register pair selected by c parity; rows g+8 are c2/c3.
#pragma unroll
        for (int ks = 0; ks < 8; ks++) {
            const int srcA = (lane & ~3) | (t4 >> 1);
            float v0 = __shfl_sync(0xffffffffu, s[ks][0], srcA);
            float v1 = __shfl_sync(0xffffffffu, s[ks][1], srcA);
            float v2 = __shfl_sync(0xffffffffu, s[ks][2], srcA);
            float v3 = __shfl_sync(0xffffffffu, s[ks][3], srcA);
            float w0 = __shfl_sync(0xffffffffu, s[ks][0], srcA + 2);
            float w1 = __shfl_sync(0xffffffffu, s[ks][1], srcA + 2);
            float w2 = __shfl_sync(0xffffffffu, s[ks][2], srcA + 2);
            float w3 = __shfl_sync(0xffffffffu, s[ks][3], srcA + 2);
            const bool odd = (t4 & 1);
            unsigned ap[4];
            ap[0] = __float_as_uint(odd ? v1 : v0);   // P[g   ][8ks+t4]
            ap[1] = __float_as_uint(odd ? v3 : v2);   // P[g+8 ][8ks+t4]
            ap[2] = __float_as_uint(odd ? w1 : w0);   // P[g   ][8ks+t4+4]
            ap[3] = __float_as_uint(odd ? w3 : w2);   // P[g+8 ][8ks+t4+4]
            const int kk = ks * 8;
#pragma unroll
            for (int ni = 0; ni < 8; ni++) {
                unsigned b0 = Vs[(size_t)(kk + t4    ) * VS_STR + ni * 8 + g];
                unsigned b1 = Vs[(size_t)(kk + t4 + 4) * VS_STR + ni * 8 + g];
                mma_tf32(o[ni], ap, b0, b1);
            }
        }
        __syncthreads();   // all warps done with KV[kt&1] before refill
    }

    // Normalize, tf32-round (g_O feeds GEMM2 raw-bit), write [B,S,D]
    const int b_ = bh >> 4;
    const int h  = bh & 15;
    float inv0 = 1.0f / l_[0];
    float inv1 = 1.0f / l_[1];
    int s0 = qb * 128 + w16 + g;
    int s1 = s0 + 8;
#pragma unroll
    for (int ni = 0; ni < 8; ni++) {
        int d2 = ni * 8 + 2 * t4;
        *(float2*)&g_O[((size_t)b_ * SEQ + s0) * DIMM + h * HDIM + d2] =
            make_float2(tfr(o[ni][0] * inv0), tfr(o[ni][1] * inv0));
        *(float2*)&g_O[((size_t)b_ * SEQ + s1) * DIMM + h * HDIM + d2] =
            make_float2(tfr(o[ni][2] * inv1), tfr(o[ni][3] * inv1));
    }
}

// ---------------------------------------------------------------------------
// Launch
// ---------------------------------------------------------------------------
extern "C" void kernel_launch(void* const* d_in, const int* in_sizes, int n_in,
                              void* d_out, int out_size)
{
    const float* x      = (const float*)d_in[0];
    const float* W_qkv  = (const float*)d_in[1];
    const float* b_qkv  = (const float*)d_in[2];
    const float* W_proj = (const float*)d_in[3];
    const float* b_proj = (const float*)d_in[4];
    float* out = (float*)d_out;

    const int gemm_smem  = 3 * GSTAGE_WORDS * (int)sizeof(unsigned);                 // 107520
    const int flash_smem = (2 * FSTAGE_WORDS + 128 * QS_STR) * (int)sizeof(unsigned); // 106496

    // Pre-pass: tf32-round x / W_qkv / W_proj into device-global copies
    {
        int n4x = (MTOK * DIMM) / 4;
        int n4q = (DIMM * NQKV) / 4;
        int n4p = (DIMM * DIMM) / 4;
        round_prepass<0><<<(n4x + 255) / 256, 256>>>(x, n4x);
        round_prepass<1><<<(n4q + 255) / 256, 256>>>(W_qkv, n4q);
        round_prepass<2><<<(n4p + 255) / 256, 256>>>(W_proj, n4p);
    }

    // GEMM1: QKV projection + scatter
    {
        cudaFuncSetAttribute(gemm_mma_kernel<true>,
                             cudaFuncAttributeMaxDynamicSharedMemorySize, gemm_smem);
        dim3 grid(NQKV / 128, MTOK / 128);   // (24, 64)
        gemm_mma_kernel<true><<<grid, 256, gemm_smem>>>(b_qkv, nullptr);
    }

    // Flash attention
    {
        cudaFuncSetAttribute(flash_mma_kernel,
                             cudaFuncAttributeMaxDynamicSharedMemorySize, flash_smem);
        dim3 grid(BATCH * NHEAD, SEQ / 128); // (64, 16)
        flash_mma_kernel<<<grid, 256, flash_smem>>>();
    }

    // GEMM2: output projection
    {
        cudaFuncSetAttribute(gemm_mma_kernel<false>,
                             cudaFuncAttributeMaxDynamicSharedMemorySize, gemm_smem);
        dim3 grid(DIMM / 128, MTOK / 128);   // (8, 64)
        gemm_mma_kernel<false><<<grid, 256, gemm_smem>>>(b_proj, out);
    }
}

// round 10
// speedup vs baseline: 1.0723x; 1.0723x over previous
#include <cuda_runtime.h>
#include <cstdint>

// Problem constants
#define DIMM   1024
#define BATCH  4
#define SEQ    2048
#define NHEAD  16
#define HDIM   64
#define MTOK   (BATCH*SEQ)        // 8192
#define NQKV   (3*DIMM)           // 3072
#define PLANE  (BATCH*NHEAD*SEQ*HDIM)  // 8388608 floats per Q/K/V plane

// Q pre-scale: 1/sqrt(64) * log2(e)  (softmax done in exp2 domain)
#define QSCALE 0.18033688011112042f

// Scratch (device globals: allocation-free per harness rules)
__device__ float g_QKV[3ULL * PLANE];            // [3][B][H][S][hd] (tf32-rounded)
__device__ float g_O[(size_t)MTOK * DIMM];       // [B,S,D] attention out (tf32-rounded)
__device__ float g_x [(size_t)MTOK * DIMM];      // tf32-rounded x
__device__ float g_Wq[(size_t)DIMM * NQKV];      // tf32-rounded W_qkv
__device__ float g_Wp[(size_t)DIMM * DIMM];      // tf32-rounded W_proj

// ---------------------------------------------------------------------------
// helpers
// ---------------------------------------------------------------------------
__device__ __forceinline__ float tfr(float x) {   // round-to-nearest tf32, as float
    unsigned u;
    asm("cvt.rna.tf32.f32 %0, %1;" : "=r"(u) : "f"(x));
    return __uint_as_float(u);
}

// mma.m16n8k8 tf32: operands already tf32-rounded -> HW truncation is lossless.
__device__ __forceinline__ void mma_tf32(float* c, const unsigned* a, unsigned b0, unsigned b1) {
    asm volatile(
        "mma.sync.aligned.m16n8k8.row.col.f32.tf32.tf32.f32 "
        "{%0,%1,%2,%3}, {%4,%5,%6,%7}, {%8,%9}, {%0,%1,%2,%3};"
        : "+f"(c[0]), "+f"(c[1]), "+f"(c[2]), "+f"(c[3])
        : "r"(a[0]), "r"(a[1]), "r"(a[2]), "r"(a[3]), "r"(b0), "r"(b1));
}

// ldmatrix x4 on 32-bit data: each 8x8 b16 matrix = 8 rows x 4 tf32 words;
// lane l receives [row l>>2][word l&3] -> exactly the 4g+t fragment pattern.
__device__ __forceinline__ void ldsm4(unsigned& r0, unsigned& r1, unsigned& r2, unsigned& r3,
                                      const void* smem_ptr) {
    unsigned sa = (unsigned)__cvta_generic_to_shared(smem_ptr);
    asm volatile("ldmatrix.sync.aligned.m8n8.x4.shared.b16 {%0,%1,%2,%3}, [%4];"
                 : "=r"(r0), "=r"(r1), "=r"(r2), "=r"(r3) : "r"(sa));
}

__device__ __forceinline__ void cp16(void* smem, const void* gmem) {
    unsigned sa = (unsigned)__cvta_generic_to_shared(smem);
    asm volatile("cp.async.cg.shared.global [%0], [%1], 16;" :: "r"(sa), "l"(gmem));
}
#define CP_COMMIT()     asm volatile("cp.async.commit_group;")
#define CP_WAIT(n)      asm volatile("cp.async.wait_group %0;" :: "n"(n))

// ---------------------------------------------------------------------------
// Pre-pass: tf32-round inputs into device-global copies. WHICH: 0=x 1=Wq 2=Wp
// ---------------------------------------------------------------------------
template<int WHICH>
__global__ void round_prepass(const float* __restrict__ src, int n4)
{
    float* dst = (WHICH == 0) ? g_x : (WHICH == 1) ? g_Wq : g_Wp;
    int i = blockIdx.x * blockDim.x + threadIdx.x;
    if (i < n4) {
        float4 v = ((const float4*)src)[i];
        v.x = tfr(v.x); v.y = tfr(v.y); v.z = tfr(v.z); v.w = tfr(v.w);
        ((float4*)dst)[i] = v;
    }
}

// ---------------------------------------------------------------------------
// Tensor-core GEMM, cp.async 3-stage ring, ONE barrier per k-tile.
// A-fragments fetched by ldmatrix.x4 (4 LDSM replaces 16 LDS per ks).
// ---------------------------------------------------------------------------
#define AS_STR 36     // 144B rows; 8 LDSM rows span distinct banks (36 mod 32 = 4)
#define BS_STR 136    // frag addr mod32 = 8t+g  (conflict-free)
#define AS_WORDS (128*AS_STR)   // 4608
#define BS_WORDS (32*BS_STR)    // 4352
#define GSTAGE_WORDS (AS_WORDS + BS_WORDS)

extern __shared__ unsigned dyn_smem[];

template<bool QKV>
__global__ __launch_bounds__(256, 2) void gemm_mma_kernel(
    const float* __restrict__ bias, float* __restrict__ out)
{
    constexpr int NC = QKV ? NQKV : DIMM;
    const float* __restrict__ A = QKV ? (const float*)g_x : (const float*)g_O;
    const float* __restrict__ W = QKV ? (const float*)g_Wq : (const float*)g_Wp;

    const int tid  = threadIdx.x;
    const int lane = tid & 31;
    const int warp = tid >> 5;
    const int g  = lane >> 2;
    const int t4 = lane & 3;
    const int m0 = (warp & 1) * 64;
    const int n0 = (warp >> 1) * 32;
    const int rowbase = blockIdx.y * 128;
    const int colbase = blockIdx.x * 128;

    // ldmatrix per-lane source coords: lanes 0-7 matrix0 (rows+0, col+0),
    // 8-15 m1 (rows+8, col+0), 16-23 m2 (rows+0, col+4), 24-31 m3 (rows+8, col+4)
    const int rowA = ((lane >> 3) & 1) * 8 + (lane & 7);
    const int colA = (lane >> 4) * 4;

    auto load_tile = [&](int buf, int k0) {
        unsigned* As = dyn_smem + buf * GSTAGE_WORDS;
        unsigned* Bs = As + AS_WORDS;
#pragma unroll
        for (int it = 0; it < 4; it++) {
            int flat = tid + it * 256;
            int r  = flat >> 3;
            int c4 = (flat & 7) * 4;
            cp16(&As[r * AS_STR + c4], &A[(size_t)(rowbase + r) * DIMM + k0 + c4]);
        }
#pragma unroll
        for (int it = 0; it < 4; it++) {
            int flat = tid + it * 256;
            int r  = flat >> 5;
            int c4 = (flat & 31) * 4;
            cp16(&Bs[r * BS_STR + c4], &W[(size_t)(k0 + r) * NC + colbase + c4]);
        }
    };

    float acc[4][4][4];
#pragma unroll
    for (int mi = 0; mi < 4; mi++)
#pragma unroll
        for (int ni = 0; ni < 4; ni++)
#pragma unroll
            for (int r = 0; r < 4; r++) acc[mi][ni][r] = 0.f;

    load_tile(0, 0);  CP_COMMIT();
    load_tile(1, 32); CP_COMMIT();

    constexpr int NT = DIMM / 32;   // 32 k-tiles
#pragma unroll 1
    for (int i = 0; i < NT; i++) {
        if (i + 1 < NT) { CP_WAIT(1); } else { CP_WAIT(0); }
        __syncthreads();             // ONE barrier per iteration

        const unsigned* As = dyn_smem + (i % 3) * GSTAGE_WORDS;
        const unsigned* Bs = As + AS_WORDS;
#pragma unroll
        for (int ks = 0; ks < 4; ks++) {
            const int kk = ks * 8;
            unsigned af[4][4];
#pragma unroll
            for (int mi = 0; mi < 4; mi++) {
                ldsm4(af[mi][0], af[mi][1], af[mi][2], af[mi][3],
                      &As[(m0 + mi * 16 + rowA) * AS_STR + colA + kk]);
            }
            unsigned bf[4][2];
#pragma unroll
            for (int ni = 0; ni < 4; ni++) {
                int col = n0 + ni * 8 + g;
                bf[ni][0] = Bs[(kk + t4    ) * BS_STR + col];
                bf[ni][1] = Bs[(kk + t4 + 4) * BS_STR + col];
            }
#pragma unroll
            for (int mi = 0; mi < 4; mi++)
#pragma unroll
                for (int ni = 0; ni < 4; ni++)
                    mma_tf32(acc[mi][ni], af[mi], bf[ni][0], bf[ni][1]);
        }

        if (i + 2 < NT) {            // safe: after compute, past sync(i)
            load_tile((i + 2) % 3, (i + 2) * 32);
            CP_COMMIT();
        }
    }

    // Epilogue
#pragma unroll
    for (int mi = 0; mi < 4; mi++) {
#pragma unroll
        for (int half = 0; half < 2; half++) {
            int m = rowbase + m0 + mi * 16 + g + half * 8;
#pragma unroll
            for (int ni = 0; ni < 4; ni++) {
                int c  = colbase + n0 + ni * 8 + 2 * t4;
                float v0 = acc[mi][ni][half * 2 + 0] + bias[c];
                float v1 = acc[mi][ni][half * 2 + 1] + bias[c + 1];
                if (QKV) {
                    int which = c >> 10;
                    int d     = c & 1023;
                    int h     = d >> 6;
                    int dd    = d & 63;
                    float sc  = (which == 0) ? QSCALE : 1.0f;
                    int b_ = m >> 11;
                    int s  = m & 2047;
                    size_t dst = (size_t)which * PLANE +
                                 (((size_t)(b_ * NHEAD + h) * SEQ + s) * HDIM) + dd;
                    *(float2*)&g_QKV[dst] = make_float2(tfr(v0 * sc), tfr(v1 * sc));
                } else {
                    *(float2*)&out[(size_t)m * DIMM + c] = make_float2(v0, v1);
                }
            }
        }
    }
}

// ---------------------------------------------------------------------------
// Flash attention. 2-stage cp.async KV ring, raw-bit tf32, exp2 softmax.
// K B-fragments and Q A-fragments via ldmatrix; P passes through per-warp
// SMEM rows (R8 path — measured faster than shuffles); V via scalar LDS.
// ---------------------------------------------------------------------------
#define KS_STR 68     // 272B rows; LDSM rows hit distinct banks (68 mod 32 = 4)
#define VS_STR 72     // V frag addr mod32 = 8t+g (conflict-free)
#define PS_STR 68
#define KS_WORDS (64*KS_STR)    // 4352
#define VS_WORDS (64*VS_STR)    // 4608
#define FSTAGE_WORDS (KS_WORDS + VS_WORDS)

__global__ __launch_bounds__(256, 2) void flash_mma_kernel()
{
    unsigned* KVB = dyn_smem;                               // [2][FSTAGE_WORDS]
    float*    Ps  = (float*)(dyn_smem + 2 * FSTAGE_WORDS);  // [128][PS_STR]: Q stage, then P

    const int bh  = blockIdx.x;
    const int qb  = blockIdx.y;
    const int tid = threadIdx.x;
    const int lane = tid & 31;
    const int warp = tid >> 5;
    const int g  = lane >> 2;
    const int t4 = lane & 3;
    const int w16 = warp * 16;

    const int rowA = ((lane >> 3) & 1) * 8 + (lane & 7);   // A-frag ldmatrix coords
    const int colA = (lane >> 4) * 4;
    const int rowB = lane & 7;                             // B-frag ldmatrix coords
    const int colB = (lane >> 3) * 4;

    const float* Qg = g_QKV + ((size_t)bh * SEQ + qb * 128) * HDIM;
    const float* Kg = g_QKV + (size_t)PLANE     + (size_t)bh * SEQ * HDIM;
    const float* Vg = g_QKV + (size_t)2 * PLANE + (size_t)bh * SEQ * HDIM;

    auto load_kv = [&](int buf, int kt) {
        unsigned* Ks = KVB + buf * FSTAGE_WORDS;
        unsigned* Vs = Ks + KS_WORDS;
#pragma unroll
        for (int it = 0; it < 4; it++) {
            int flat = tid + it * 256;
            int r  = flat >> 4;
            int c4 = (flat & 15) * 4;
            size_t gsrc = ((size_t)kt * 64 + r) * HDIM + c4;
            cp16(&Ks[r * KS_STR + c4], &Kg[gsrc]);
            cp16(&Vs[r * VS_STR + c4], &Vg[gsrc]);
        }
    };

    load_kv(0, 0);
    CP_COMMIT();

    // Stage Q (128x64; pre-rounded + pre-scaled in GEMM1)
#pragma unroll
    for (int it = 0; it < 8; it++) {
        int flat = tid + it * 256;
        int r  = flat >> 4;
        int c4 = (flat & 15) * 4;
        *(float4*)&Ps[r * PS_STR + c4] = *(const float4*)&Qg[(size_t)r * HDIM + c4];
    }
    __syncthreads();

    unsigned aq[8][4];
#pragma unroll
    for (int ks = 0; ks < 8; ks++) {
        ldsm4(aq[ks][0], aq[ks][1], aq[ks][2], aq[ks][3],
              &Ps[(w16 + rowA) * PS_STR + colA + ks * 8]);
    }

    float m_[2] = {-1e30f, -1e30f};
    float l_[2] = {0.f, 0.f};
    float o[8][4];
#pragma unroll
    for (int ni = 0; ni < 8; ni++)
#pragma unroll
        for (int r = 0; r < 4; r++) o[ni][r] = 0.f;

    constexpr int NT = SEQ / 64;   // 32 KV tiles
#pragma unroll 1
    for (int kt = 0; kt < NT; kt++) {
        if (kt + 1 < NT) {
            load_kv((kt + 1) & 1, kt + 1);
            CP_COMMIT();
            CP_WAIT(1);
        } else {
            CP_WAIT(0);
        }
        __syncthreads();

        const unsigned* Ks = KVB + (kt & 1) * FSTAGE_WORDS;
        const unsigned* Vs = Ks + KS_WORDS;

        // S = Q @ K^T. K B-frags via ldmatrix.x4: matrices cover cols
        // {kk, kk+4, kk+8, kk+12} of rows ni*8..ni*8+7 -> two ks steps per LDSM.
        float s[8][4];
#pragma unroll
        for (int ni = 0; ni < 8; ni++)
#pragma unroll
            for (int r = 0; r < 4; r++) s[ni][r] = 0.f;

#pragma unroll
        for (int ni = 0; ni < 8; ni++) {
            const unsigned* kb = &Ks[(ni * 8 + rowB) * KS_STR + colB];
#pragma unroll
            for (int ks2 = 0; ks2 < 4; ks2++) {
                unsigned b0a, b1a, b0b, b1b;
                ldsm4(b0a, b1a, b0b, b1b, kb + ks2 * 16);
                mma_tf32(s[ni], aq[2 * ks2    ], b0a, b1a);
                mma_tf32(s[ni], aq[2 * ks2 + 1], b0b, b1b);
            }
        }

        // Online softmax (exp2 domain), rows g and g+8, reduce over 4 t-lanes
        float mx0 = -1e30f, mx1 = -1e30f;
#pragma unroll
        for (int ni = 0; ni < 8; ni++) {
            mx0 = fmaxf(mx0, fmaxf(s[ni][0], s[ni][1]));
            mx1 = fmaxf(mx1, fmaxf(s[ni][2], s[ni][3]));
        }
        mx0 = fmaxf(mx0, __shfl_xor_sync(0xffffffffu, mx0, 1));
        mx0 = fmaxf(mx0, __shfl_xor_sync(0xffffffffu, mx0, 2));
        mx1 = fmaxf(mx1, __shfl_xor_sync(0xffffffffu, mx1, 1));
        mx1 = fmaxf(mx1, __shfl_xor_sync(0xffffffffu, mx1, 2));

        float mn0 = fmaxf(m_[0], mx0);
        float mn1 = fmaxf(m_[1], mx1);
        float corr0 = exp2f(m_[0] - mn0);
        float corr1 = exp2f(m_[1] - mn1);
        m_[0] = mn0; m_[1] = mn1;

        // P rounded to tf32; denominator summed from the SAME rounded values.
        float lp0 = 0.f, lp1 = 0.f;
#pragma unroll
        for (int ni = 0; ni < 8; ni++) {
            s[ni][0] = tfr(exp2f(s[ni][0] - mn0));
            s[ni][1] = tfr(exp2f(s[ni][1] - mn0));
            s[ni][2] = tfr(exp2f(s[ni][2] - mn1));
            s[ni][3] = tfr(exp2f(s[ni][3] - mn1));
            lp0 += s[ni][0] + s[ni][1];
            lp1 += s[ni][2] + s[ni][3];
            o[ni][0] *= corr0; o[ni][1] *= corr0;
            o[ni][2] *= corr1; o[ni][3] *= corr1;
        }
        lp0 += __shfl_xor_sync(0xffffffffu, lp0, 1);
        lp0 += __shfl_xor_sync(0xffffffffu, lp0, 2);
        lp1 += __shfl_xor_sync(0xffffffffu, lp1, 1);
        lp1 += __shfl_xor_sync(0xffffffffu, lp1, 2);
        l_[0] = l_[0] * corr0 + lp0;
        l_[1] = l_[1] * corr1 + lp1;

        // Store P into this warp's Ps rows (C-layout -> A-layout re-fragment)
        __syncwarp();
#pragma unroll
        for (int ni = 0; ni < 8; ni++) {
            int c = ni * 8 + 2 * t4;
            *(float2*)&Ps[(w16 + g    ) * PS_STR + c] = make_float2(s[ni][0], s[ni][1]);
            *(float2*)&Ps[(w16 + g + 8) * PS_STR + c] = make_float2(s[ni][2], s[ni][3]);
        }
        __syncwarp();

        // O += P @ V. P A-frags via ldmatrix; V B-frags via scalar LDS
        // (transposed pattern — ldmatrix not applicable to 32-bit there).
#pragma unroll
        for (int ks = 0; ks < 8; ks++) {
            unsigned ap[4];
            ldsm4(ap[0], ap[1], ap[2], ap[3],
                  &Ps[(w16 + rowA) * PS_STR + colA + ks * 8]);
            const int kk = ks * 8;
#pragma unroll
            for (int ni = 0; ni < 8; ni++) {
                unsigned b0 = Vs[(size_t)(kk + t4    ) * VS_STR + ni * 8 + g];
                unsigned b1 = Vs[(size_t)(kk + t4 + 4) * VS_STR + ni * 8 + g];
                mma_tf32(o[ni], ap, b0, b1);
            }
        }
        __syncthreads();   // all warps done with KV[kt&1] before refill
    }

    // Normalize, tf32-round (g_O feeds GEMM2 raw-bit), write [B,S,D]
    const int b_ = bh >> 4;
    const int h  = bh & 15;
    float inv0 = 1.0f / l_[0];
    float inv1 = 1.0f / l_[1];
    int s0 = qb * 128 + w16 + g;
    int s1 = s0 + 8;
#pragma unroll
    for (int ni = 0; ni < 8; ni++) {
        int d2 = ni * 8 + 2 * t4;
        *(float2*)&g_O[((size_t)b_ * SEQ + s0) * DIMM + h * HDIM + d2] =
            make_float2(tfr(o[ni][0] * inv0), tfr(o[ni][1] * inv0));
        *(float2*)&g_O[((size_t)b_ * SEQ + s1) * DIMM + h * HDIM + d2] =
            make_float2(tfr(o[ni][2] * inv1), tfr(o[ni][3] * inv1));
    }
}

// ---------------------------------------------------------------------------
// Launch
// ---------------------------------------------------------------------------
extern "C" void kernel_launch(void* const* d_in, const int* in_sizes, int n_in,
                              void* d_out, int out_size)
{
    const float* x      = (const float*)d_in[0];
    const float* W_qkv  = (const float*)d_in[1];
    const float* b_qkv  = (const float*)d_in[2];
    const float* W_proj = (const float*)d_in[3];
    const float* b_proj = (const float*)d_in[4];
    float* out = (float*)d_out;

    const int gemm_smem  = 3 * GSTAGE_WORDS * (int)sizeof(unsigned);                  // 107520
    const int flash_smem = (2 * FSTAGE_WORDS + 128 * PS_STR) * (int)sizeof(unsigned); // 106496

    // Pre-pass: tf32-round x / W_qkv / W_proj into device-global copies
    {
        int n4x = (MTOK * DIMM) / 4;
        int n4q = (DIMM * NQKV) / 4;
        int n4p = (DIMM * DIMM) / 4;
        round_prepass<0><<<(n4x + 255) / 256, 256>>>(x, n4x);
        round_prepass<1><<<(n4q + 255) / 256, 256>>>(W_qkv, n4q);
        round_prepass<2><<<(n4p + 255) / 256, 256>>>(W_proj, n4p);
    }

    // GEMM1: QKV projection + scatter
    {
        cudaFuncSetAttribute(gemm_mma_kernel<true>,
                             cudaFuncAttributeMaxDynamicSharedMemorySize, gemm_smem);
        dim3 grid(NQKV / 128, MTOK / 128);   // (24, 64)
        gemm_mma_kernel<true><<<grid, 256, gemm_smem>>>(b_qkv, nullptr);
    }

    // Flash attention
    {
        cudaFuncSetAttribute(flash_mma_kernel,
                             cudaFuncAttributeMaxDynamicSharedMemorySize, flash_smem);
        dim3 grid(BATCH * NHEAD, SEQ / 128); // (64, 16)
        flash_mma_kernel<<<grid, 256, flash_smem>>>();
    }

    // GEMM2: output projection
    {
        cudaFuncSetAttribute(gemm_mma_kernel<false>,
                             cudaFuncAttributeMaxDynamicSharedMemorySize, gemm_smem);
        dim3 grid(DIMM / 128, MTOK / 128);   // (8, 64)
        gemm_mma_kernel<false><<<grid, 256, gemm_smem>>>(b_proj, out);
    }
}